// round 16
// baseline (speedup 1.0000x reference)
#include <cuda_runtime.h>
#include <cuda_fp16.h>
#include <cstdint>

#define TOK   8192
#define DIMN  512
#define SEQ   512
#define NBAT  16
#define FFD   2048
#define CBSZ  8192
#define CBD   64
#define NSP2  128

__device__ float g_h  [TOK * DIMN];
__device__ half  g_lnhb[TOK * DIMN];
__device__ half  g_lnhs[TOK * DIMN];
__device__ float g_qb [TOK * DIMN];
__device__ float g_kb [TOK * DIMN];
__device__ float g_vb [TOK * DIMN];
__device__ float g_att[TOK * DIMN];
__device__ float g_ffb[TOK * FFD];
__device__ float g_z  [TOK * CBD];
__device__ float g_cn [CBSZ];
__device__ float g_cbt[CBD * CBSZ];
__device__ float g_bv2[NSP2][TOK];
__device__ int   g_bc2[NSP2][TOK];
__device__ int   g_idx[TOK];
__device__ float g_part[NBAT];

enum { EPI_NONE = 0, EPI_BIAS = 1, EPI_BIAS_POS = 2, EPI_RES = 3,
       EPI_RES_BIAS = 4, EPI_GELU_BIAS = 5 };

__device__ __forceinline__ float gelu_f(float x) {
    float x3 = x * x * x;
    float t  = tanhf(0.7978845608028654f * (x + 0.044715f * x3));
    return 0.5f * x * (1.0f + t);
}

__device__ __forceinline__ void split2(float x, float y,
                                       uint32_t& big, uint32_t& sml) {
    half bx = __float2half_rn(x);
    half by = __float2half_rn(y);
    half sx = __float2half_rn(x - __half2float(bx));
    half sy = __float2half_rn(y - __half2float(by));
    half2 b = __halves2half2(bx, by);
    half2 s = __halves2half2(sx, sy);
    big = *(uint32_t*)&b;
    sml = *(uint32_t*)&s;
}

__device__ __forceinline__ void mma16816(float* d, const uint32_t* a,
                                         uint32_t b0, uint32_t b1) {
    asm volatile(
        "mma.sync.aligned.m16n8k16.row.col.f32.f16.f16.f32 "
        "{%0,%1,%2,%3}, {%4,%5,%6,%7}, {%8,%9}, {%0,%1,%2,%3};"
        : "+f"(d[0]), "+f"(d[1]), "+f"(d[2]), "+f"(d[3])
        : "r"(a[0]), "r"(a[1]), "r"(a[2]), "r"(a[3]), "r"(b0), "r"(b1));
}

// ---------------------------------------------------------------------------
// Shared pieces
// ---------------------------------------------------------------------------
#define BUF_W 10240
#define TG_SMEM (2 * BUF_W * 4)

#define LOAD_B_CHUNK(k0)                                                      \
    {                                                                         \
        _Pragma("unroll")                                                     \
        for (int kk = 0; kk < 16; kk++) {                                     \
            pbv[kk] = 0.f;                                                    \
            if (inb)                                                          \
                pbv[kk] = B[(long long)((k0) + lbkh * 16 + kk) * Nn + col0 + lbn]; \
        }                                                                     \
    }

#define STORE_B_CHUNK(base)                                                   \
    {                                                                         \
        uint32_t* Bbw = (base) + 5120;                                        \
        uint32_t* Bsw = (base) + 7680;                                        \
        uint32_t bw[8], sw[8];                                                \
        _Pragma("unroll")                                                     \
        for (int p = 0; p < 8; p++)                                           \
            split2(pbv[2 * p], pbv[2 * p + 1], bw[p], sw[p]);                 \
        int bo = lbn * 20 + lbkh * 8;                                         \
        *(uint4*)(Bbw + bo)     = make_uint4(bw[0], bw[1], bw[2], bw[3]);     \
        *(uint4*)(Bbw + bo + 4) = make_uint4(bw[4], bw[5], bw[6], bw[7]);     \
        *(uint4*)(Bsw + bo)     = make_uint4(sw[0], sw[1], sw[2], sw[3]);     \
        *(uint4*)(Bsw + bo + 4) = make_uint4(sw[4], sw[5], sw[6], sw[7]);     \
    }

#define GEMM_VARS                                                             \
    extern __shared__ uint32_t smw[];                                         \
    const int tid  = threadIdx.x;                                             \
    const int lane = tid & 31;                                                \
    const int w    = tid >> 5;                                                \
    const int wm   = w & 3;                                                   \
    const int wn   = w >> 2;                                                  \
    const int m0w  = wm * 32;                                                 \
    const int n0w  = wn * 64;                                                 \
    const int g    = lane >> 2;                                               \
    const int tg   = lane & 3;                                                \
    const int lar  = tid >> 2;                                                \
    const int lakq = (tid & 3) << 2;                                          \
    const int lbn  = tid & 127;                                               \
    const int lbkh = tid >> 7;                                                \
    const bool inb = (col0 + lbn) < Nn;                                       \
    float acc[2][8][4];                                                       \
    _Pragma("unroll")                                                         \
    for (int i = 0; i < 2; i++)                                               \
        _Pragma("unroll")                                                     \
        for (int j = 0; j < 8; j++)                                           \
            _Pragma("unroll")                                                 \
            for (int q = 0; q < 4; q++) acc[i][j][q] = 0.f;

#define MMA_LOOP(Abw, Asw, Bbw, Bsw)                                          \
    _Pragma("unroll")                                                         \
    for (int ks = 0; ks < 2; ks++) {                                          \
        const int ko = ks << 3;                                               \
        uint32_t fab[2][4], fas[2][4];                                        \
        _Pragma("unroll")                                                     \
        for (int i = 0; i < 2; i++) {                                         \
            int rb = m0w + i * 16 + g;                                        \
            fab[i][0] = Abw[rb * 20 + ko + tg];                               \
            fab[i][1] = Abw[(rb + 8) * 20 + ko + tg];                         \
            fab[i][2] = Abw[rb * 20 + ko + tg + 4];                           \
            fab[i][3] = Abw[(rb + 8) * 20 + ko + tg + 4];                     \
            fas[i][0] = Asw[rb * 20 + ko + tg];                               \
            fas[i][1] = Asw[(rb + 8) * 20 + ko + tg];                         \
            fas[i][2] = Asw[rb * 20 + ko + tg + 4];                           \
            fas[i][3] = Asw[(rb + 8) * 20 + ko + tg + 4];                     \
        }                                                                     \
        _Pragma("unroll")                                                     \
        for (int j = 0; j < 8; j++) {                                         \
            int nb = n0w + j * 8 + g;                                         \
            uint32_t bb0 = Bbw[nb * 20 + ko + tg];                            \
            uint32_t bb1 = Bbw[nb * 20 + ko + tg + 4];                        \
            uint32_t bs0 = Bsw[nb * 20 + ko + tg];                            \
            uint32_t bs1 = Bsw[nb * 20 + ko + tg + 4];                        \
            _Pragma("unroll")                                                 \
            for (int i = 0; i < 2; i++) {                                     \
                mma16816(acc[i][j], fab[i], bb0, bb1);                        \
                mma16816(acc[i][j], fab[i], bs0, bs1);                        \
                mma16816(acc[i][j], fas[i], bb0, bb1);                        \
            }                                                                 \
        }                                                                     \
    }

#define GEMM_EPILOGUE                                                         \
    _Pragma("unroll")                                                         \
    for (int i = 0; i < 2; i++) {                                             \
        int r = row0 + m0w + i * 16 + g;                                      \
        _Pragma("unroll")                                                     \
        for (int j = 0; j < 8; j++) {                                         \
            int cc = col0 + n0w + j * 8 + 2 * tg;                             \
            if (cc >= Nn) continue;                                           \
            float2 v0 = make_float2(acc[i][j][0], acc[i][j][1]);              \
            float2 v1 = make_float2(acc[i][j][2], acc[i][j][3]);              \
            if (epi == EPI_BIAS || epi == EPI_RES_BIAS ||                     \
                epi == EPI_GELU_BIAS || epi == EPI_BIAS_POS) {                \
                float2 b2 = *(const float2*)(bias + cc);                      \
                v0.x += b2.x; v0.y += b2.y;                                   \
                v1.x += b2.x; v1.y += b2.y;                                   \
            }                                                                 \
            if (epi == EPI_BIAS_POS) {                                        \
                float2 p0 = *(const float2*)(extra + (long long)(r & (SEQ - 1)) * Nn + cc); \
                float2 p1 = *(const float2*)(extra + (long long)((r + 8) & (SEQ - 1)) * Nn + cc); \
                v0.x += p0.x; v0.y += p0.y;                                   \
                v1.x += p1.x; v1.y += p1.y;                                   \
            }                                                                 \
            if (epi == EPI_RES || epi == EPI_RES_BIAS) {                      \
                float2 e0 = *(const float2*)(extra + (long long)r * Nn + cc); \
                float2 e1 = *(const float2*)(extra + (long long)(r + 8) * Nn + cc); \
                v0.x += e0.x; v0.y += e0.y;                                   \
                v1.x += e1.x; v1.y += e1.y;                                   \
            }                                                                 \
            if (epi == EPI_GELU_BIAS) {                                       \
                v0.x = gelu_f(v0.x); v0.y = gelu_f(v0.y);                     \
                v1.x = gelu_f(v1.x); v1.y = gelu_f(v1.y);                     \
            }                                                                 \
            *(float2*)(C + (long long)r * Nn + cc) = v0;                      \
            *(float2*)(C + (long long)(r + 8) * Nn + cc) = v1;                \
        }                                                                     \
    }

// ---------------------------------------------------------------------------
// tgemm_k: fp32 A (splits in-kernel) — R8/R12 proven version
// ---------------------------------------------------------------------------
__global__ __launch_bounds__(256, 2)
void tgemm_k(const float* __restrict__ A, const float* __restrict__ B,
             float* __restrict__ C, const float* __restrict__ bias,
             const float* __restrict__ extra, int Nn, int K, int epi)
{
    const int row0 = blockIdx.y * 128;
    const int col0 = blockIdx.x * 128;
    GEMM_VARS
    float4 pa[4];
    float  pbv[16];

#define LOAD_A_F(k0)                                                          \
    _Pragma("unroll")                                                         \
    for (int v = 0; v < 2; v++)                                               \
        _Pragma("unroll")                                                     \
        for (int kb = 0; kb < 2; kb++)                                        \
            pa[v * 2 + kb] = *(const float4*)(A +                             \
                (long long)(row0 + lar + v * 64) * K + (k0) + kb * 16 + lakq);

#define STORE_A_F(base)                                                       \
    {                                                                         \
        uint32_t* Abw = (base);                                               \
        uint32_t* Asw = (base) + 2560;                                        \
        _Pragma("unroll")                                                     \
        for (int v = 0; v < 2; v++)                                           \
            _Pragma("unroll")                                                 \
            for (int kb = 0; kb < 2; kb++) {                                  \
                float4 t = pa[v * 2 + kb];                                    \
                uint32_t b0, s0, b1, s1;                                      \
                split2(t.x, t.y, b0, s0);                                     \
                split2(t.z, t.w, b1, s1);                                     \
                int wo = (lar + v * 64) * 20 + kb * 8 + (lakq >> 1);          \
                Abw[wo] = b0; Abw[wo + 1] = b1;                               \
                Asw[wo] = s0; Asw[wo + 1] = s1;                               \
            }                                                                 \
    }

    LOAD_A_F(0)
    LOAD_B_CHUNK(0)
    STORE_A_F(smw)
    STORE_B_CHUNK(smw)
    __syncthreads();
    const int nc = K >> 5;
    for (int c = 0; c < nc; c++) {
        const int p = c & 1;
        uint32_t* Abw = smw + p * BUF_W;
        uint32_t* Asw = Abw + 2560;
        uint32_t* Bbw = Abw + 5120;
        uint32_t* Bsw = Abw + 7680;
        if (c + 1 < nc) { LOAD_A_F((c + 1) << 5) LOAD_B_CHUNK((c + 1) << 5) }
        MMA_LOOP(Abw, Asw, Bbw, Bsw)
        if (c + 1 < nc) {
            STORE_A_F(smw + (p ^ 1) * BUF_W)
            STORE_B_CHUNK(smw + (p ^ 1) * BUF_W)
            __syncthreads();
        }
    }
#undef LOAD_A_F
#undef STORE_A_F
    GEMM_EPILOGUE
}

// ---------------------------------------------------------------------------
// tgemmh_k: A pre-split (half big/small, row-major) — no A-side split2.
// ---------------------------------------------------------------------------
__global__ __launch_bounds__(256, 2)
void tgemmh_k(const half* __restrict__ Ahb, const half* __restrict__ Ahs,
              const float* __restrict__ B, float* __restrict__ C,
              const float* __restrict__ bias, const float* __restrict__ extra,
              int Nn, int K, int epi)
{
    const int row0 = blockIdx.y * 128;
    const int col0 = blockIdx.x * 128;
    GEMM_VARS
    uint2 pab2[4], pas2[4];
    float pbv[16];

#define LOAD_A_H(k0)                                                          \
    _Pragma("unroll")                                                         \
    for (int v = 0; v < 2; v++)                                               \
        _Pragma("unroll")                                                     \
        for (int kb = 0; kb < 2; kb++) {                                      \
            long long ai = (long long)(row0 + lar + v * 64) * K + (k0) + kb * 16 + lakq; \
            pab2[v * 2 + kb] = *(const uint2*)(Ahb + ai);                     \
            pas2[v * 2 + kb] = *(const uint2*)(Ahs + ai);                     \
        }

#define STORE_A_H(base)                                                       \
    {                                                                         \
        uint32_t* Abw = (base);                                               \
        uint32_t* Asw = (base) + 2560;                                        \
        _Pragma("unroll")                                                     \
        for (int v = 0; v < 2; v++)                                           \
            _Pragma("unroll")                                                 \
            for (int kb = 0; kb < 2; kb++) {                                  \
                int wo = (lar + v * 64) * 20 + kb * 8 + (lakq >> 1);          \
                *(uint2*)(Abw + wo) = pab2[v * 2 + kb];                       \
                *(uint2*)(Asw + wo) = pas2[v * 2 + kb];                       \
            }                                                                 \
    }

    LOAD_A_H(0)
    LOAD_B_CHUNK(0)
    STORE_A_H(smw)
    STORE_B_CHUNK(smw)
    __syncthreads();
    const int nc = K >> 5;
    for (int c = 0; c < nc; c++) {
        const int p = c & 1;
        uint32_t* Abw = smw + p * BUF_W;
        uint32_t* Asw = Abw + 2560;
        uint32_t* Bbw = Abw + 5120;
        uint32_t* Bsw = Abw + 7680;
        if (c + 1 < nc) { LOAD_A_H((c + 1) << 5) LOAD_B_CHUNK((c + 1) << 5) }
        MMA_LOOP(Abw, Asw, Bbw, Bsw)
        if (c + 1 < nc) {
            STORE_A_H(smw + (p ^ 1) * BUF_W)
            STORE_B_CHUNK(smw + (p ^ 1) * BUF_W)
            __syncthreads();
        }
    }
#undef LOAD_A_H
#undef STORE_A_H
    GEMM_EPILOGUE
}

// ---------------------------------------------------------------------------
// VQ argmax GEMM (R12 WIN, unchanged structure)
// ---------------------------------------------------------------------------
__global__ __launch_bounds__(256, 2)
void vq_mma_k(const float* __restrict__ A, const float* __restrict__ B,
              int Nn, int K)
{
    const int row0 = blockIdx.y * 128;
    const int col0 = blockIdx.x * 128;
    GEMM_VARS
    float4 pa[4];
    float  pbv[16];

#define LOAD_A_F(k0)                                                          \
    _Pragma("unroll")                                                         \
    for (int v = 0; v < 2; v++)                                               \
        _Pragma("unroll")                                                     \
        for (int kb = 0; kb < 2; kb++)                                        \
            pa[v * 2 + kb] = *(const float4*)(A +                             \
                (long long)(row0 + lar + v * 64) * K + (k0) + kb * 16 + lakq);

#define STORE_A_F(base)                                                       \
    {                                                                         \
        uint32_t* Abw = (base);                                               \
        uint32_t* Asw = (base) + 2560;                                        \
        _Pragma("unroll")                                                     \
        for (int v = 0; v < 2; v++)                                           \
            _Pragma("unroll")                                                 \
            for (int kb = 0; kb < 2; kb++) {                                  \
                float4 t = pa[v * 2 + kb];                                    \
                uint32_t b0, s0, b1, s1;                                      \
                split2(t.x, t.y, b0, s0);                                     \
                split2(t.z, t.w, b1, s1);                                     \
                int wo = (lar + v * 64) * 20 + kb * 8 + (lakq >> 1);          \
                Abw[wo] = b0; Abw[wo + 1] = b1;                               \
                Asw[wo] = s0; Asw[wo + 1] = s1;                               \
            }                                                                 \
    }

    LOAD_A_F(0)
    LOAD_B_CHUNK(0)
    STORE_A_F(smw)
    STORE_B_CHUNK(smw)
    __syncthreads();
    const int nc = K >> 5;
    for (int c = 0; c < nc; c++) {
        const int p = c & 1;
        uint32_t* Abw = smw + p * BUF_W;
        uint32_t* Asw = Abw + 2560;
        uint32_t* Bbw = Abw + 5120;
        uint32_t* Bsw = Abw + 7680;
        if (c + 1 < nc) { LOAD_A_F((c + 1) << 5) LOAD_B_CHUNK((c + 1) << 5) }
        MMA_LOOP(Abw, Asw, Bbw, Bsw)
        if (c + 1 < nc) {
            STORE_A_F(smw + (p ^ 1) * BUF_W)
            STORE_B_CHUNK(smw + (p ^ 1) * BUF_W)
            __syncthreads();
        }
    }
#undef LOAD_A_F
#undef STORE_A_F

    const int sp = blockIdx.x * 2 + wn;
#pragma unroll
    for (int i = 0; i < 2; i++) {
        int r = row0 + m0w + i * 16 + g;
        float bv0 = -1e30f, bv1 = -1e30f;
        int bc0 = 0, bc1 = 0;
#pragma unroll
        for (int j = 0; j < 8; j++) {
            int cc = col0 + n0w + j * 8 + 2 * tg;
            float cn0 = g_cn[cc], cn1 = g_cn[cc + 1];
            float s0 = acc[i][j][0] - cn0;
            float s1 = acc[i][j][1] - cn1;
            float s2 = acc[i][j][2] - cn0;
            float s3 = acc[i][j][3] - cn1;
            if (s0 > bv0) { bv0 = s0; bc0 = cc; }
            if (s1 > bv0) { bv0 = s1; bc0 = cc + 1; }
            if (s2 > bv1) { bv1 = s2; bc1 = cc; }
            if (s3 > bv1) { bv1 = s3; bc1 = cc + 1; }
        }
#pragma unroll
        for (int off = 1; off <= 2; off <<= 1) {
            float ov = __shfl_xor_sync(0xffffffffu, bv0, off);
            int   oc = __shfl_xor_sync(0xffffffffu, bc0, off);
            if (ov > bv0 || (ov == bv0 && oc < bc0)) { bv0 = ov; bc0 = oc; }
            ov = __shfl_xor_sync(0xffffffffu, bv1, off);
            oc = __shfl_xor_sync(0xffffffffu, bc1, off);
            if (ov > bv1 || (ov == bv1 && oc < bc1)) { bv1 = ov; bc1 = oc; }
        }
        if (tg == 0) {
            g_bv2[sp][r] = bv0;     g_bc2[sp][r] = bc0;
            g_bv2[sp][r + 8] = bv1; g_bc2[sp][r + 8] = bc1;
        }
    }
}

// ---------------------------------------------------------------------------
// LayerNorm: warp per row; emits pre-split half big/small.
// ---------------------------------------------------------------------------
__global__ __launch_bounds__(256)
void layernorm_k(const float* __restrict__ X, half* __restrict__ Yb,
                 half* __restrict__ Ys,
                 const float* __restrict__ gg, const float* __restrict__ bb)
{
    const int row  = blockIdx.x * 8 + (threadIdx.x >> 5);
    const int lane = threadIdx.x & 31;
    const float* x = X + (long long)row * DIMN;
    float4 v[4];
    float s = 0.f, q = 0.f;
#pragma unroll
    for (int i = 0; i < 4; i++) {
        v[i] = *(const float4*)(x + i * 128 + lane * 4);
        s += v[i].x + v[i].y + v[i].z + v[i].w;
        q += v[i].x * v[i].x + v[i].y * v[i].y + v[i].z * v[i].z + v[i].w * v[i].w;
    }
#pragma unroll
    for (int off = 16; off; off >>= 1) {
        s += __shfl_xor_sync(0xffffffffu, s, off);
        q += __shfl_xor_sync(0xffffffffu, q, off);
    }
    float mu  = s * (1.0f / DIMN);
    float var = q * (1.0f / DIMN) - mu * mu;
    float inv = 1.0f / sqrtf(var + 1e-5f);
#pragma unroll
    for (int i = 0; i < 4; i++) {
        float4 g4 = *(const float4*)(gg + i * 128 + lane * 4);
        float4 b4 = *(const float4*)(bb + i * 128 + lane * 4);
        float4 o;
        o.x = (v[i].x - mu) * inv * g4.x + b4.x;
        o.y = (v[i].y - mu) * inv * g4.y + b4.y;
        o.z = (v[i].z - mu) * inv * g4.z + b4.z;
        o.w = (v[i].w - mu) * inv * g4.w + b4.w;
        uint32_t b0, s0, b1, s1;
        split2(o.x, o.y, b0, s0);
        split2(o.z, o.w, b1, s1);
        long long idx = (long long)row * DIMN + i * 128 + lane * 4;
        *(uint2*)(Yb + idx) = make_uint2(b0, b1);
        *(uint2*)(Ys + idx) = make_uint2(s0, s1);
    }
}

// ---------------------------------------------------------------------------
// Fused flash attention (R15 WIN, unchanged)
// ---------------------------------------------------------------------------
#define FA_QB 0
#define FA_QS 2304
#define FA_KB 4608
#define FA_KS 6912
#define FA_VB 9216
#define FA_VS 11520
#define FA_SMEM (13824 * 4)

__global__ __launch_bounds__(128, 4)
void fattn_k(const float* __restrict__ Q, const float* __restrict__ K,
             const float* __restrict__ V, float* __restrict__ O)
{
    extern __shared__ uint32_t fsm[];
    const int tid  = threadIdx.x;
    const int lane = tid & 31;
    const int w    = tid >> 5;
    const int g    = lane >> 2;
    const int tg   = lane & 3;
    const int qt   = blockIdx.x, bh = blockIdx.y;
    const int b    = bh >> 3, h = bh & 7;

    const float* Qg = Q + ((long long)(b * SEQ + qt * 64)) * DIMN + h * 64;

#pragma unroll
    for (int i = 0; i < 8; i++) {
        int f = tid + (i << 7);
        int r = f >> 4, cq = f & 15;
        float4 v = *(const float4*)(Qg + (long long)r * DIMN + cq * 4);
        uint32_t b0, s0, b1, s1;
        split2(v.x, v.y, b0, s0);
        split2(v.z, v.w, b1, s1);
        int o = r * 36 + cq * 2;
        fsm[FA_QB + o] = b0; fsm[FA_QB + o + 1] = b1;
        fsm[FA_QS + o] = s0; fsm[FA_QS + o + 1] = s1;
    }
    __syncthreads();

    const int qr = w * 16 + g;

    float m0 = -1e30f, m1 = -1e30f, l0 = 0.f, l1 = 0.f;
    float oa[8][4];
#pragma unroll
    for (int j = 0; j < 8; j++)
#pragma unroll
        for (int q = 0; q < 4; q++) oa[j][q] = 0.f;

    const int r2  = tid & 31;
    const int cgV = tid >> 5;

    for (int kt = 0; kt < 8; kt++) {
        const float* Kg = K + ((long long)(b * SEQ + kt * 64)) * DIMN + h * 64;
        const float* Vg = V + ((long long)(b * SEQ + kt * 64)) * DIMN + h * 64;

        __syncthreads();
#pragma unroll
        for (int i = 0; i < 8; i++) {
            int f = tid + (i << 7);
            int r = f >> 4, cq = f & 15;
            float4 v = *(const float4*)(Kg + (long long)r * DIMN + cq * 4);
            uint32_t b0, s0, b1, s1;
            split2(v.x, v.y, b0, s0);
            split2(v.z, v.w, b1, s1);
            int o = r * 36 + cq * 2;
            fsm[FA_KB + o] = b0; fsm[FA_KB + o + 1] = b1;
            fsm[FA_KS + o] = s0; fsm[FA_KS + o + 1] = s1;
        }
#pragma unroll
        for (int i = 0; i < 4; i++) {
            int c0 = cgV * 16 + i * 4;
            float4 va = *(const float4*)(Vg + (long long)(2 * r2) * DIMN + c0);
            float4 vb = *(const float4*)(Vg + (long long)(2 * r2 + 1) * DIMN + c0);
            float av[4] = {va.x, va.y, va.z, va.w};
            float bv[4] = {vb.x, vb.y, vb.z, vb.w};
#pragma unroll
            for (int k = 0; k < 4; k++) {
                uint32_t big, sml;
                split2(av[k], bv[k], big, sml);
                fsm[FA_VB + (c0 + k) * 36 + r2] = big;
                fsm[FA_VS + (c0 + k) * 36 + r2] = sml;
            }
        }
        __syncthreads();

        float s[8][4];
#pragma unroll
        for (int j = 0; j < 8; j++)
#pragma unroll
            for (int q = 0; q < 4; q++) s[j][q] = 0.f;
#pragma unroll
        for (int kg = 0; kg < 4; kg++) {
            uint32_t qfb[4], qfs[4];
            int ba = qr * 36 + kg * 8 + tg;
            qfb[0] = fsm[FA_QB + ba];
            qfb[1] = fsm[FA_QB + ba + 288];
            qfb[2] = fsm[FA_QB + ba + 4];
            qfb[3] = fsm[FA_QB + ba + 292];
            qfs[0] = fsm[FA_QS + ba];
            qfs[1] = fsm[FA_QS + ba + 288];
            qfs[2] = fsm[FA_QS + ba + 4];
            qfs[3] = fsm[FA_QS + ba + 292];
            const int ko = kg * 8 + tg;
#pragma unroll
            for (int j = 0; j < 8; j++) {
                int nb = j * 8 + g;
                uint32_t kb0 = fsm[FA_KB + nb * 36 + ko];
                uint32_t kb1 = fsm[FA_KB + nb * 36 + ko + 4];
                uint32_t ks0 = fsm[FA_KS + nb * 36 + ko];
                uint32_t ks1 = fsm[FA_KS + nb * 36 + ko + 4];
                mma16816(s[j], qfb, kb0, kb1);
                mma16816(s[j], qfb, ks0, ks1);
                mma16816(s[j], qfs, kb0, kb1);
            }
        }

        float ml0 = -1e30f, ml1 = -1e30f;
#pragma unroll
        for (int j = 0; j < 8; j++) {
            s[j][0] *= 0.125f; s[j][1] *= 0.125f;
            s[j][2] *= 0.125f; s[j][3] *= 0.125f;
            ml0 = fmaxf(ml0, fmaxf(s[j][0], s[j][1]));
            ml1 = fmaxf(ml1, fmaxf(s[j][2], s[j][3]));
        }
        ml0 = fmaxf(ml0, __shfl_xor_sync(0xffffffffu, ml0, 1));
        ml0 = fmaxf(ml0, __shfl_xor_sync(0xffffffffu, ml0, 2));
        ml1 = fmaxf(ml1, __shfl_xor_sync(0xffffffffu, ml1, 1));
        ml1 = fmaxf(ml1, __shfl_xor_sync(0xffffffffu, ml1, 2));
        float mn0 = fmaxf(m0, ml0), mn1 = fmaxf(m1, ml1);
        float sc0 = __expf(m0 - mn0), sc1 = __expf(m1 - mn1);
        float rs0 = 0.f, rs1 = 0.f;
#pragma unroll
        for (int j = 0; j < 8; j++) {
            s[j][0] = __expf(s[j][0] - mn0);
            s[j][1] = __expf(s[j][1] - mn0);
            s[j][2] = __expf(s[j][2] - mn1);
            s[j][3] = __expf(s[j][3] - mn1);
            rs0 += s[j][0] + s[j][1];
            rs1 += s[j][2] + s[j][3];
        }
        rs0 += __shfl_xor_sync(0xffffffffu, rs0, 1);
        rs0 += __shfl_xor_sync(0xffffffffu, rs0, 2);
        rs1 += __shfl_xor_sync(0xffffffffu, rs1, 1);
        rs1 += __shfl_xor_sync(0xffffffffu, rs1, 2);
        l0 = l0 * sc0 + rs0;
        l1 = l1 * sc1 + rs1;
        m0 = mn0; m1 = mn1;
#pragma unroll
        for (int j = 0; j < 8; j++) {
            oa[j][0] *= sc0; oa[j][1] *= sc0;
            oa[j][2] *= sc1; oa[j][3] *= sc1;
        }

#pragma unroll
        for (int kg = 0; kg < 4; kg++) {
            uint32_t pab[4], pas[4];
            int j0 = 2 * kg, j1 = 2 * kg + 1;
            split2(s[j0][0], s[j0][1], pab[0], pas[0]);
            split2(s[j0][2], s[j0][3], pab[1], pas[1]);
            split2(s[j1][0], s[j1][1], pab[2], pas[2]);
            split2(s[j1][2], s[j1][3], pab[3], pas[3]);
            const int ko = kg * 8 + tg;
#pragma unroll
            for (int jo = 0; jo < 8; jo++) {
                int nb = jo * 8 + g;
                uint32_t vb0 = fsm[FA_VB + nb * 36 + ko];
                uint32_t vb1 = fsm[FA_VB + nb * 36 + ko + 4];
                uint32_t vs0 = fsm[FA_VS + nb * 36 + ko];
                uint32_t vs1 = fsm[FA_VS + nb * 36 + ko + 4];
                mma16816(oa[jo], pab, vb0, vb1);
                mma16816(oa[jo], pab, vs0, vs1);
                mma16816(oa[jo], pas, vb0, vb1);
            }
        }
    }

    float inv0 = 1.0f / l0, inv1 = 1.0f / l1;
    int row0 = b * SEQ + qt * 64 + w * 16 + g;
#pragma unroll
    for (int jo = 0; jo < 8; jo++) {
        int col = h * 64 + jo * 8 + 2 * tg;
        *(float2*)(O + (long long)row0 * DIMN + col) =
            make_float2(oa[jo][0] * inv0, oa[jo][1] * inv0);
        *(float2*)(O + (long long)(row0 + 8) * DIMN + col) =
            make_float2(oa[jo][2] * inv1, oa[jo][3] * inv1);
    }
}

// ---------------------------------------------------------------------------
// VQ helpers (unchanged)
// ---------------------------------------------------------------------------
__global__ void cb_norm_k(const float* __restrict__ cb)
{
    int c = blockIdx.x * 256 + threadIdx.x;
    float s = 0.f;
    const float* p = cb + (long long)c * CBD;
#pragma unroll 8
    for (int d = 0; d < CBD; d++) { float v = p[d]; s += v * v; }
    g_cn[c] = 0.5f * s;
}

__global__ void cbt_k(const float* __restrict__ cb)
{
    __shared__ float t[32][33];
    const int c0 = blockIdx.x * 32, d0 = blockIdx.y * 32;
    const int tx = threadIdx.x, ty = threadIdx.y;
#pragma unroll
    for (int i = 0; i < 4; i++)
        t[ty + i * 8][tx] = cb[(long long)(c0 + ty + i * 8) * CBD + d0 + tx];
    __syncthreads();
#pragma unroll
    for (int i = 0; i < 4; i++)
        g_cbt[(long long)(d0 + ty + i * 8) * CBSZ + c0 + tx] = t[tx][ty + i * 8];
}

__global__ void vq_combine_k()
{
    int t = blockIdx.x * 256 + threadIdx.x;
    float bv = g_bv2[0][t]; int bc = g_bc2[0][t];
#pragma unroll 8
    for (int s = 1; s < NSP2; s++) {
        float v = g_bv2[s][t]; int c = g_bc2[s][t];
        if (v > bv) { bv = v; bc = c; }
    }
    g_idx[t] = bc;
}

__global__ void vq_reduce_k(const float* __restrict__ cb,
                            const float* __restrict__ Z,
                            float* __restrict__ out)
{
    __shared__ float ssum[256];
    __shared__ float sloss[256];
    const int b = blockIdx.x;
    const int tid = threadIdx.x;
    const int d = tid & 63;
    const int sg = tid >> 6;
    float sum = 0.f, loss = 0.f;
    for (int s = sg; s < SEQ; s += 4) {
        int c = g_idx[b * SEQ + s];
        float qv = cb[(long long)c * CBD + d];
        float zv = Z[((long long)b * SEQ + s) * CBD + d];
        sum += qv;
        float dd = qv - zv;
        loss += dd * dd;
    }
    ssum[tid] = sum; sloss[tid] = loss;
    __syncthreads();
    if (tid < 64)
        out[b * CBD + tid] = ssum[tid] + ssum[tid + 64] + ssum[tid + 128] + ssum[tid + 192];
    for (int st = 128; st > 0; st >>= 1) {
        if (tid < st) sloss[tid] += sloss[tid + st];
        __syncthreads();
    }
    if (tid == 0) g_part[b] = sloss[0];
}

__global__ void vq_finish_k(float* __restrict__ out, int out_size)
{
    if (threadIdx.x == 0 && out_size > NBAT * CBD) {
        float s = 0.f;
        for (int i = 0; i < NBAT; i++) s += g_part[i];
        out[NBAT * CBD] = s / (float)(TOK * CBD);
    }
}

// ---------------------------------------------------------------------------
// Launch
// ---------------------------------------------------------------------------
extern "C" void kernel_launch(void* const* d_in, const int* in_sizes, int n_in,
                              void* d_out, int out_size)
{
    (void)in_sizes; (void)n_in;
    const float* x    = (const float*)d_in[0];
    const float* w_in = (const float*)d_in[1];
    const float* b_in = (const float*)d_in[2];
    const float* pos  = (const float*)d_in[3];
    const float* ln1g = (const float*)d_in[4];
    const float* ln1b = (const float*)d_in[5];
    const float* wq   = (const float*)d_in[6];
    const float* wk   = (const float*)d_in[7];
    const float* wv   = (const float*)d_in[8];
    const float* wo   = (const float*)d_in[9];
    const float* ln2g = (const float*)d_in[10];
    const float* ln2b = (const float*)d_in[11];
    const float* fw1  = (const float*)d_in[12];
    const float* fb1  = (const float*)d_in[13];
    const float* fw2  = (const float*)d_in[14];
    const float* fb2  = (const float*)d_in[15];
    const float* lnfg = (const float*)d_in[16];
    const float* lnfb = (const float*)d_in[17];
    const float* wout = (const float*)d_in[18];
    const float* bout = (const float*)d_in[19];
    const float* cbk  = (const float*)d_in[20];
    float* out = (float*)d_out;

    float *h, *qb, *kb, *vb, *att, *ff, *z, *cbt;
    half *lnb, *lns;
    cudaGetSymbolAddress((void**)&h,   g_h);
    cudaGetSymbolAddress((void**)&lnb, g_lnhb);
    cudaGetSymbolAddress((void**)&lns, g_lnhs);
    cudaGetSymbolAddress((void**)&qb,  g_qb);
    cudaGetSymbolAddress((void**)&kb,  g_kb);
    cudaGetSymbolAddress((void**)&vb,  g_vb);
    cudaGetSymbolAddress((void**)&att, g_att);
    cudaGetSymbolAddress((void**)&ff,  g_ffb);
    cudaGetSymbolAddress((void**)&z,   g_z);
    cudaGetSymbolAddress((void**)&cbt, g_cbt);

    cudaFuncSetAttribute(tgemm_k, cudaFuncAttributeMaxDynamicSharedMemorySize, TG_SMEM);
    cudaFuncSetAttribute(tgemmh_k, cudaFuncAttributeMaxDynamicSharedMemorySize, TG_SMEM);
    cudaFuncSetAttribute(vq_mma_k, cudaFuncAttributeMaxDynamicSharedMemorySize, TG_SMEM);
    cudaFuncSetAttribute(fattn_k, cudaFuncAttributeMaxDynamicSharedMemorySize, FA_SMEM);

    const dim3 g512(4, 64), g2048(16, 64), g64(1, 64);

    tgemm_k<<<g512, 256, TG_SMEM>>>(x, w_in, h, b_in, pos, DIMN, DIMN, EPI_BIAS_POS);

    for (int l = 0; l < 4; l++) {
        layernorm_k<<<TOK / 8, 256>>>(h, lnb, lns, ln1g + l * DIMN, ln1b + l * DIMN);
        tgemmh_k<<<g512, 256, TG_SMEM>>>(lnb, lns, wq + (long long)l * DIMN * DIMN, qb, nullptr, nullptr, DIMN, DIMN, EPI_NONE);
        tgemmh_k<<<g512, 256, TG_SMEM>>>(lnb, lns, wk + (long long)l * DIMN * DIMN, kb, nullptr, nullptr, DIMN, DIMN, EPI_NONE);
        tgemmh_k<<<g512, 256, TG_SMEM>>>(lnb, lns, wv + (long long)l * DIMN * DIMN, vb, nullptr, nullptr, DIMN, DIMN, EPI_NONE);
        fattn_k<<<dim3(8, 128), 128, FA_SMEM>>>(qb, kb, vb, att);
        tgemm_k<<<g512, 256, TG_SMEM>>>(att, wo + (long long)l * DIMN * DIMN, h, nullptr, h, DIMN, DIMN, EPI_RES);
        layernorm_k<<<TOK / 8, 256>>>(h, lnb, lns, ln2g + l * DIMN, ln2b + l * DIMN);
        tgemmh_k<<<g2048, 256, TG_SMEM>>>(lnb, lns, fw1 + (long long)l * DIMN * FFD, ff, fb1 + l * FFD, nullptr, FFD, DIMN, EPI_GELU_BIAS);
        tgemm_k<<<g512, 256, TG_SMEM>>>(ff, fw2 + (long long)l * FFD * DIMN, h, fb2 + l * DIMN, h, DIMN, FFD, EPI_RES_BIAS);
    }

    layernorm_k<<<TOK / 8, 256>>>(h, lnb, lns, lnfg, lnfb);
    tgemmh_k<<<g64, 256, TG_SMEM>>>(lnb, lns, wout, z, bout, nullptr, CBD, DIMN, EPI_BIAS);

    cb_norm_k<<<CBSZ / 256, 256>>>(cbk);
    cbt_k<<<dim3(CBSZ / 32, CBD / 32), dim3(32, 8)>>>(cbk);
    vq_mma_k<<<dim3(CBSZ / 128, TOK / 128), 256, TG_SMEM>>>(z, cbt, CBSZ, CBD);
    vq_combine_k<<<TOK / 256, 256>>>();
    vq_reduce_k<<<NBAT, 256>>>(cbk, z, out);
    vq_finish_k<<<1, 32>>>(out, out_size);
}

// round 17
// speedup vs baseline: 1.0485x; 1.0485x over previous
#include <cuda_runtime.h>
#include <cuda_fp16.h>
#include <cstdint>

#define TOK   8192
#define DIMN  512
#define SEQ   512
#define NBAT  16
#define FFD   2048
#define CBSZ  8192
#define CBD   64
#define NSP2  128

__device__ float g_h  [TOK * DIMN];
__device__ float g_lnb[TOK * DIMN];
__device__ float g_qb [TOK * DIMN];
__device__ float g_kb [TOK * DIMN];
__device__ float g_vb [TOK * DIMN];
__device__ float g_att[TOK * DIMN];
__device__ float g_ffb[TOK * FFD];
__device__ float g_z  [TOK * CBD];
__device__ float g_cn [CBSZ];
__device__ float g_cbt[CBD * CBSZ];
__device__ float g_bv2[NSP2][TOK];
__device__ int   g_bc2[NSP2][TOK];
__device__ int   g_idx[TOK];
__device__ float g_part[NBAT];

enum { EPI_NONE = 0, EPI_BIAS = 1, EPI_BIAS_POS = 2, EPI_RES = 3,
       EPI_RES_BIAS = 4, EPI_GELU_BIAS = 5 };

__device__ __forceinline__ float gelu_f(float x) {
    float x3 = x * x * x;
    float t  = tanhf(0.7978845608028654f * (x + 0.044715f * x3));
    return 0.5f * x * (1.0f + t);
}

__device__ __forceinline__ void split2(float x, float y,
                                       uint32_t& big, uint32_t& sml) {
    half bx = __float2half_rn(x);
    half by = __float2half_rn(y);
    half sx = __float2half_rn(x - __half2float(bx));
    half sy = __float2half_rn(y - __half2float(by));
    half2 b = __halves2half2(bx, by);
    half2 s = __halves2half2(sx, sy);
    big = *(uint32_t*)&b;
    sml = *(uint32_t*)&s;
}

__device__ __forceinline__ void mma16816(float* d, const uint32_t* a,
                                         uint32_t b0, uint32_t b1) {
    asm volatile(
        "mma.sync.aligned.m16n8k16.row.col.f32.f16.f16.f32 "
        "{%0,%1,%2,%3}, {%4,%5,%6,%7}, {%8,%9}, {%0,%1,%2,%3};"
        : "+f"(d[0]), "+f"(d[1]), "+f"(d[2]), "+f"(d[3])
        : "r"(a[0]), "r"(a[1]), "r"(a[2]), "r"(a[3]), "r"(b0), "r"(b1));
}

// ---------------------------------------------------------------------------
// fp16x3 GEMM core (R8/R12 WIN body). row0/col0 defined by caller.
// ---------------------------------------------------------------------------
#define BUF_W 10240
#define TG_SMEM (2 * BUF_W * 4)

#define LOAD_CHUNK(k0)                                                        \
    {                                                                         \
        _Pragma("unroll")                                                     \
        for (int v = 0; v < 2; v++)                                           \
            _Pragma("unroll")                                                 \
            for (int kb = 0; kb < 2; kb++)                                    \
                pa[v * 2 + kb] = *(const float4*)(A +                         \
                    (long long)(row0 + lar + v * 64) * K + (k0) + kb * 16 + lakq); \
        _Pragma("unroll")                                                     \
        for (int kk = 0; kk < 16; kk++) {                                     \
            pbv[kk] = 0.f;                                                    \
            if (inb)                                                          \
                pbv[kk] = B[(long long)((k0) + lbkh * 16 + kk) * Nn + col0 + lbn]; \
        }                                                                     \
    }

#define STORE_CHUNK(base)                                                     \
    {                                                                         \
        uint32_t* Abw = (base);                                               \
        uint32_t* Asw = (base) + 2560;                                        \
        uint32_t* Bbw = (base) + 5120;                                        \
        uint32_t* Bsw = (base) + 7680;                                        \
        _Pragma("unroll")                                                     \
        for (int v = 0; v < 2; v++)                                           \
            _Pragma("unroll")                                                 \
            for (int kb = 0; kb < 2; kb++) {                                  \
                float4 t = pa[v * 2 + kb];                                    \
                uint32_t b0, s0, b1, s1;                                      \
                split2(t.x, t.y, b0, s0);                                     \
                split2(t.z, t.w, b1, s1);                                     \
                int wo = (lar + v * 64) * 20 + kb * 8 + (lakq >> 1);          \
                Abw[wo] = b0; Abw[wo + 1] = b1;                               \
                Asw[wo] = s0; Asw[wo + 1] = s1;                               \
            }                                                                 \
        uint32_t bw[8], sw[8];                                                \
        _Pragma("unroll")                                                     \
        for (int p = 0; p < 8; p++)                                           \
            split2(pbv[2 * p], pbv[2 * p + 1], bw[p], sw[p]);                 \
        int bo = lbn * 20 + lbkh * 8;                                         \
        *(uint4*)(Bbw + bo)     = make_uint4(bw[0], bw[1], bw[2], bw[3]);     \
        *(uint4*)(Bbw + bo + 4) = make_uint4(bw[4], bw[5], bw[6], bw[7]);     \
        *(uint4*)(Bsw + bo)     = make_uint4(sw[0], sw[1], sw[2], sw[3]);     \
        *(uint4*)(Bsw + bo + 4) = make_uint4(sw[4], sw[5], sw[6], sw[7]);     \
    }

#define GEMM_BODY                                                             \
    extern __shared__ uint32_t smw[];                                         \
    const int tid  = threadIdx.x;                                             \
    const int lane = tid & 31;                                                \
    const int w    = tid >> 5;                                                \
    const int wm   = w & 3;                                                   \
    const int wn   = w >> 2;                                                  \
    const int m0w  = wm * 32;                                                 \
    const int n0w  = wn * 64;                                                 \
    const int g    = lane >> 2;                                               \
    const int tg   = lane & 3;                                                \
    const int lar  = tid >> 2;                                                \
    const int lakq = (tid & 3) << 2;                                          \
    const int lbn  = tid & 127;                                               \
    const int lbkh = tid >> 7;                                                \
    const bool inb = (col0 + lbn) < Nn;                                       \
    float acc[2][8][4];                                                       \
    _Pragma("unroll")                                                         \
    for (int i = 0; i < 2; i++)                                               \
        _Pragma("unroll")                                                     \
        for (int j = 0; j < 8; j++)                                           \
            _Pragma("unroll")                                                 \
            for (int q = 0; q < 4; q++) acc[i][j][q] = 0.f;                   \
    float4 pa[4];                                                             \
    float  pbv[16];                                                           \
    LOAD_CHUNK(0)                                                             \
    STORE_CHUNK(smw)                                                          \
    __syncthreads();                                                          \
    const int nc = K >> 5;                                                    \
    for (int c = 0; c < nc; c++) {                                            \
        const int p = c & 1;                                                  \
        uint32_t* Abw = smw + p * BUF_W;                                      \
        uint32_t* Asw = Abw + 2560;                                           \
        uint32_t* Bbw = Abw + 5120;                                           \
        uint32_t* Bsw = Abw + 7680;                                           \
        if (c + 1 < nc) LOAD_CHUNK((c + 1) << 5)                              \
        _Pragma("unroll")                                                     \
        for (int ks = 0; ks < 2; ks++) {                                      \
            const int ko = ks << 3;                                           \
            uint32_t fab[2][4], fas[2][4];                                    \
            _Pragma("unroll")                                                 \
            for (int i = 0; i < 2; i++) {                                     \
                int rb = m0w + i * 16 + g;                                    \
                fab[i][0] = Abw[rb * 20 + ko + tg];                           \
                fab[i][1] = Abw[(rb + 8) * 20 + ko + tg];                     \
                fab[i][2] = Abw[rb * 20 + ko + tg + 4];                       \
                fab[i][3] = Abw[(rb + 8) * 20 + ko + tg + 4];                 \
                fas[i][0] = Asw[rb * 20 + ko + tg];                           \
                fas[i][1] = Asw[(rb + 8) * 20 + ko + tg];                     \
                fas[i][2] = Asw[rb * 20 + ko + tg + 4];                       \
                fas[i][3] = Asw[(rb + 8) * 20 + ko + tg + 4];                 \
            }                                                                 \
            _Pragma("unroll")                                                 \
            for (int j = 0; j < 8; j++) {                                     \
                int nb = n0w + j * 8 + g;                                     \
                uint32_t bb0 = Bbw[nb * 20 + ko + tg];                        \
                uint32_t bb1 = Bbw[nb * 20 + ko + tg + 4];                    \
                uint32_t bs0 = Bsw[nb * 20 + ko + tg];                        \
                uint32_t bs1 = Bsw[nb * 20 + ko + tg + 4];                    \
                _Pragma("unroll")                                             \
                for (int i = 0; i < 2; i++) {                                 \
                    mma16816(acc[i][j], fab[i], bb0, bb1);                    \
                    mma16816(acc[i][j], fab[i], bs0, bs1);                    \
                    mma16816(acc[i][j], fas[i], bb0, bb1);                    \
                }                                                             \
            }                                                                 \
        }                                                                     \
        if (c + 1 < nc) {                                                     \
            STORE_CHUNK(smw + (p ^ 1) * BUF_W)                                \
            __syncthreads();                                                  \
        }                                                                     \
    }

__global__ __launch_bounds__(256, 2)
void tgemm_k(const float* __restrict__ A, const float* __restrict__ B,
             float* __restrict__ C, const float* __restrict__ bias,
             const float* __restrict__ extra, int Nn, int K, int epi)
{
    const int row0 = blockIdx.y * 128;
    const int col0 = blockIdx.x * 128;
    GEMM_BODY

#pragma unroll
    for (int i = 0; i < 2; i++) {
        int r = row0 + m0w + i * 16 + g;
#pragma unroll
        for (int j = 0; j < 8; j++) {
            int cc = col0 + n0w + j * 8 + 2 * tg;
            if (cc >= Nn) continue;
            float2 v0 = make_float2(acc[i][j][0], acc[i][j][1]);
            float2 v1 = make_float2(acc[i][j][2], acc[i][j][3]);
            if (epi == EPI_BIAS || epi == EPI_RES_BIAS ||
                epi == EPI_GELU_BIAS || epi == EPI_BIAS_POS) {
                float2 b2 = *(const float2*)(bias + cc);
                v0.x += b2.x; v0.y += b2.y;
                v1.x += b2.x; v1.y += b2.y;
            }
            if (epi == EPI_BIAS_POS) {
                float2 p0 = *(const float2*)(extra + (long long)(r & (SEQ - 1)) * Nn + cc);
                float2 p1 = *(const float2*)(extra + (long long)((r + 8) & (SEQ - 1)) * Nn + cc);
                v0.x += p0.x; v0.y += p0.y;
                v1.x += p1.x; v1.y += p1.y;
            }
            if (epi == EPI_RES || epi == EPI_RES_BIAS) {
                float2 e0 = *(const float2*)(extra + (long long)r * Nn + cc);
                float2 e1 = *(const float2*)(extra + (long long)(r + 8) * Nn + cc);
                v0.x += e0.x; v0.y += e0.y;
                v1.x += e1.x; v1.y += e1.y;
            }
            if (epi == EPI_GELU_BIAS) {
                v0.x = gelu_f(v0.x); v0.y = gelu_f(v0.y);
                v1.x = gelu_f(v1.x); v1.y = gelu_f(v1.y);
            }
            *(float2*)(C + (long long)r * Nn + cc) = v0;
            *(float2*)(C + (long long)(r + 8) * Nn + cc) = v1;
        }
    }
}

// ---------------------------------------------------------------------------
// VQ argmax GEMM (R12 WIN, unchanged)
// ---------------------------------------------------------------------------
__global__ __launch_bounds__(256, 2)
void vq_mma_k(const float* __restrict__ A, const float* __restrict__ B,
              int Nn, int K)
{
    const int row0 = blockIdx.y * 128;
    const int col0 = blockIdx.x * 128;
    GEMM_BODY

    const int sp = blockIdx.x * 2 + wn;
#pragma unroll
    for (int i = 0; i < 2; i++) {
        int r = row0 + m0w + i * 16 + g;
        float bv0 = -1e30f, bv1 = -1e30f;
        int bc0 = 0, bc1 = 0;
#pragma unroll
        for (int j = 0; j < 8; j++) {
            int cc = col0 + n0w + j * 8 + 2 * tg;
            float cn0 = g_cn[cc], cn1 = g_cn[cc + 1];
            float s0 = acc[i][j][0] - cn0;
            float s1 = acc[i][j][1] - cn1;
            float s2 = acc[i][j][2] - cn0;
            float s3 = acc[i][j][3] - cn1;
            if (s0 > bv0) { bv0 = s0; bc0 = cc; }
            if (s1 > bv0) { bv0 = s1; bc0 = cc + 1; }
            if (s2 > bv1) { bv1 = s2; bc1 = cc; }
            if (s3 > bv1) { bv1 = s3; bc1 = cc + 1; }
        }
#pragma unroll
        for (int off = 1; off <= 2; off <<= 1) {
            float ov = __shfl_xor_sync(0xffffffffu, bv0, off);
            int   oc = __shfl_xor_sync(0xffffffffu, bc0, off);
            if (ov > bv0 || (ov == bv0 && oc < bc0)) { bv0 = ov; bc0 = oc; }
            ov = __shfl_xor_sync(0xffffffffu, bv1, off);
            oc = __shfl_xor_sync(0xffffffffu, bc1, off);
            if (ov > bv1 || (ov == bv1 && oc < bc1)) { bv1 = ov; bc1 = oc; }
        }
        if (tg == 0) {
            g_bv2[sp][r] = bv0;     g_bc2[sp][r] = bc0;
            g_bv2[sp][r + 8] = bv1; g_bc2[sp][r + 8] = bc1;
        }
    }
}

// ---------------------------------------------------------------------------
// LayerNorm: warp per row (R14/R15 WIN version, fp32 out)
// ---------------------------------------------------------------------------
__global__ __launch_bounds__(256)
void layernorm_k(const float* __restrict__ X, float* __restrict__ Y,
                 const float* __restrict__ gg, const float* __restrict__ bb)
{
    const int row  = blockIdx.x * 8 + (threadIdx.x >> 5);
    const int lane = threadIdx.x & 31;
    const float* x = X + (long long)row * DIMN;
    float4 v[4];
    float s = 0.f, q = 0.f;
#pragma unroll
    for (int i = 0; i < 4; i++) {
        v[i] = *(const float4*)(x + i * 128 + lane * 4);
        s += v[i].x + v[i].y + v[i].z + v[i].w;
        q += v[i].x * v[i].x + v[i].y * v[i].y + v[i].z * v[i].z + v[i].w * v[i].w;
    }
#pragma unroll
    for (int off = 16; off; off >>= 1) {
        s += __shfl_xor_sync(0xffffffffu, s, off);
        q += __shfl_xor_sync(0xffffffffu, q, off);
    }
    float mu  = s * (1.0f / DIMN);
    float var = q * (1.0f / DIMN) - mu * mu;
    float inv = 1.0f / sqrtf(var + 1e-5f);
    float* y = Y + (long long)row * DIMN;
#pragma unroll
    for (int i = 0; i < 4; i++) {
        float4 g4 = *(const float4*)(gg + i * 128 + lane * 4);
        float4 b4 = *(const float4*)(bb + i * 128 + lane * 4);
        float4 o;
        o.x = (v[i].x - mu) * inv * g4.x + b4.x;
        o.y = (v[i].y - mu) * inv * g4.y + b4.y;
        o.z = (v[i].z - mu) * inv * g4.z + b4.z;
        o.w = (v[i].w - mu) * inv * g4.w + b4.w;
        *(float4*)(y + i * 128 + lane * 4) = o;
    }
}

// ---------------------------------------------------------------------------
// Fused flash attention (R15 WIN, unchanged)
// ---------------------------------------------------------------------------
#define FA_QB 0
#define FA_QS 2304
#define FA_KB 4608
#define FA_KS 6912
#define FA_VB 9216
#define FA_VS 11520
#define FA_SMEM (13824 * 4)

__global__ __launch_bounds__(128, 4)
void fattn_k(const float* __restrict__ Q, const float* __restrict__ K,
             const float* __restrict__ V, float* __restrict__ O)
{
    extern __shared__ uint32_t fsm[];
    const int tid  = threadIdx.x;
    const int lane = tid & 31;
    const int w    = tid >> 5;
    const int g    = lane >> 2;
    const int tg   = lane & 3;
    const int qt   = blockIdx.x, bh = blockIdx.y;
    const int b    = bh >> 3, h = bh & 7;

    const float* Qg = Q + ((long long)(b * SEQ + qt * 64)) * DIMN + h * 64;

#pragma unroll
    for (int i = 0; i < 8; i++) {
        int f = tid + (i << 7);
        int r = f >> 4, cq = f & 15;
        float4 v = *(const float4*)(Qg + (long long)r * DIMN + cq * 4);
        uint32_t b0, s0, b1, s1;
        split2(v.x, v.y, b0, s0);
        split2(v.z, v.w, b1, s1);
        int o = r * 36 + cq * 2;
        fsm[FA_QB + o] = b0; fsm[FA_QB + o + 1] = b1;
        fsm[FA_QS + o] = s0; fsm[FA_QS + o + 1] = s1;
    }
    __syncthreads();

    const int qr = w * 16 + g;

    float m0 = -1e30f, m1 = -1e30f, l0 = 0.f, l1 = 0.f;
    float oa[8][4];
#pragma unroll
    for (int j = 0; j < 8; j++)
#pragma unroll
        for (int q = 0; q < 4; q++) oa[j][q] = 0.f;

    const int r2  = tid & 31;
    const int cgV = tid >> 5;

    for (int kt = 0; kt < 8; kt++) {
        const float* Kg = K + ((long long)(b * SEQ + kt * 64)) * DIMN + h * 64;
        const float* Vg = V + ((long long)(b * SEQ + kt * 64)) * DIMN + h * 64;

        __syncthreads();
#pragma unroll
        for (int i = 0; i < 8; i++) {
            int f = tid + (i << 7);
            int r = f >> 4, cq = f & 15;
            float4 v = *(const float4*)(Kg + (long long)r * DIMN + cq * 4);
            uint32_t b0, s0, b1, s1;
            split2(v.x, v.y, b0, s0);
            split2(v.z, v.w, b1, s1);
            int o = r * 36 + cq * 2;
            fsm[FA_KB + o] = b0; fsm[FA_KB + o + 1] = b1;
            fsm[FA_KS + o] = s0; fsm[FA_KS + o + 1] = s1;
        }
#pragma unroll
        for (int i = 0; i < 4; i++) {
            int c0 = cgV * 16 + i * 4;
            float4 va = *(const float4*)(Vg + (long long)(2 * r2) * DIMN + c0);
            float4 vb = *(const float4*)(Vg + (long long)(2 * r2 + 1) * DIMN + c0);
            float av[4] = {va.x, va.y, va.z, va.w};
            float bv[4] = {vb.x, vb.y, vb.z, vb.w};
#pragma unroll
            for (int k = 0; k < 4; k++) {
                uint32_t big, sml;
                split2(av[k], bv[k], big, sml);
                fsm[FA_VB + (c0 + k) * 36 + r2] = big;
                fsm[FA_VS + (c0 + k) * 36 + r2] = sml;
            }
        }
        __syncthreads();

        float s[8][4];
#pragma unroll
        for (int j = 0; j < 8; j++)
#pragma unroll
            for (int q = 0; q < 4; q++) s[j][q] = 0.f;
#pragma unroll
        for (int kg = 0; kg < 4; kg++) {
            uint32_t qfb[4], qfs[4];
            int ba = qr * 36 + kg * 8 + tg;
            qfb[0] = fsm[FA_QB + ba];
            qfb[1] = fsm[FA_QB + ba + 288];
            qfb[2] = fsm[FA_QB + ba + 4];
            qfb[3] = fsm[FA_QB + ba + 292];
            qfs[0] = fsm[FA_QS + ba];
            qfs[1] = fsm[FA_QS + ba + 288];
            qfs[2] = fsm[FA_QS + ba + 4];
            qfs[3] = fsm[FA_QS + ba + 292];
            const int ko = kg * 8 + tg;
#pragma unroll
            for (int j = 0; j < 8; j++) {
                int nb = j * 8 + g;
                uint32_t kb0 = fsm[FA_KB + nb * 36 + ko];
                uint32_t kb1 = fsm[FA_KB + nb * 36 + ko + 4];
                uint32_t ks0 = fsm[FA_KS + nb * 36 + ko];
                uint32_t ks1 = fsm[FA_KS + nb * 36 + ko + 4];
                mma16816(s[j], qfb, kb0, kb1);
                mma16816(s[j], qfb, ks0, ks1);
                mma16816(s[j], qfs, kb0, kb1);
            }
        }

        float ml0 = -1e30f, ml1 = -1e30f;
#pragma unroll
        for (int j = 0; j < 8; j++) {
            s[j][0] *= 0.125f; s[j][1] *= 0.125f;
            s[j][2] *= 0.125f; s[j][3] *= 0.125f;
            ml0 = fmaxf(ml0, fmaxf(s[j][0], s[j][1]));
            ml1 = fmaxf(ml1, fmaxf(s[j][2], s[j][3]));
        }
        ml0 = fmaxf(ml0, __shfl_xor_sync(0xffffffffu, ml0, 1));
        ml0 = fmaxf(ml0, __shfl_xor_sync(0xffffffffu, ml0, 2));
        ml1 = fmaxf(ml1, __shfl_xor_sync(0xffffffffu, ml1, 1));
        ml1 = fmaxf(ml1, __shfl_xor_sync(0xffffffffu, ml1, 2));
        float mn0 = fmaxf(m0, ml0), mn1 = fmaxf(m1, ml1);
        float sc0 = __expf(m0 - mn0), sc1 = __expf(m1 - mn1);
        float rs0 = 0.f, rs1 = 0.f;
#pragma unroll
        for (int j = 0; j < 8; j++) {
            s[j][0] = __expf(s[j][0] - mn0);
            s[j][1] = __expf(s[j][1] - mn0);
            s[j][2] = __expf(s[j][2] - mn1);
            s[j][3] = __expf(s[j][3] - mn1);
            rs0 += s[j][0] + s[j][1];
            rs1 += s[j][2] + s[j][3];
        }
        rs0 += __shfl_xor_sync(0xffffffffu, rs0, 1);
        rs0 += __shfl_xor_sync(0xffffffffu, rs0, 2);
        rs1 += __shfl_xor_sync(0xffffffffu, rs1, 1);
        rs1 += __shfl_xor_sync(0xffffffffu, rs1, 2);
        l0 = l0 * sc0 + rs0;
        l1 = l1 * sc1 + rs1;
        m0 = mn0; m1 = mn1;
#pragma unroll
        for (int j = 0; j < 8; j++) {
            oa[j][0] *= sc0; oa[j][1] *= sc0;
            oa[j][2] *= sc1; oa[j][3] *= sc1;
        }

#pragma unroll
        for (int kg = 0; kg < 4; kg++) {
            uint32_t pab[4], pas[4];
            int j0 = 2 * kg, j1 = 2 * kg + 1;
            split2(s[j0][0], s[j0][1], pab[0], pas[0]);
            split2(s[j0][2], s[j0][3], pab[1], pas[1]);
            split2(s[j1][0], s[j1][1], pab[2], pas[2]);
            split2(s[j1][2], s[j1][3], pab[3], pas[3]);
            const int ko = kg * 8 + tg;
#pragma unroll
            for (int jo = 0; jo < 8; jo++) {
                int nb = jo * 8 + g;
                uint32_t vb0 = fsm[FA_VB + nb * 36 + ko];
                uint32_t vb1 = fsm[FA_VB + nb * 36 + ko + 4];
                uint32_t vs0 = fsm[FA_VS + nb * 36 + ko];
                uint32_t vs1 = fsm[FA_VS + nb * 36 + ko + 4];
                mma16816(oa[jo], pab, vb0, vb1);
                mma16816(oa[jo], pab, vs0, vs1);
                mma16816(oa[jo], pas, vb0, vb1);
            }
        }
    }

    float inv0 = 1.0f / l0, inv1 = 1.0f / l1;
    int row0 = b * SEQ + qt * 64 + w * 16 + g;
#pragma unroll
    for (int jo = 0; jo < 8; jo++) {
        int col = h * 64 + jo * 8 + 2 * tg;
        *(float2*)(O + (long long)row0 * DIMN + col) =
            make_float2(oa[jo][0] * inv0, oa[jo][1] * inv0);
        *(float2*)(O + (long long)(row0 + 8) * DIMN + col) =
            make_float2(oa[jo][2] * inv1, oa[jo][3] * inv1);
    }
}

// ---------------------------------------------------------------------------
// VQ prep: transpose codebook AND compute 0.5*||c||^2 in one kernel.
// grid (CBSZ/32, CBD/32); d0==0 blocks also accumulate norms across all d.
// ---------------------------------------------------------------------------
__global__ void cbt_k(const float* __restrict__ cb)
{
    __shared__ float t[32][33];
    const int c0 = blockIdx.x * 32, d0 = blockIdx.y * 32;
    const int tx = threadIdx.x, ty = threadIdx.y;
#pragma unroll
    for (int i = 0; i < 4; i++)
        t[ty + i * 8][tx] = cb[(long long)(c0 + ty + i * 8) * CBD + d0 + tx];
    __syncthreads();
#pragma unroll
    for (int i = 0; i < 4; i++)
        g_cbt[(long long)(d0 + ty + i * 8) * CBSZ + c0 + tx] = t[tx][ty + i * 8];
    // norms: one warp-row subset (ty==0) of d0==0 blocks computes full norms
    if (d0 == 0 && ty == 0) {
        int c = c0 + tx;
        const float* p = cb + (long long)c * CBD;
        float s = 0.f;
#pragma unroll 8
        for (int d = 0; d < CBD; d++) { float v = p[d]; s += v * v; }
        g_cn[c] = 0.5f * s;
    }
}

__global__ void vq_combine_k()
{
    int t = blockIdx.x * 256 + threadIdx.x;
    float bv = g_bv2[0][t]; int bc = g_bc2[0][t];
#pragma unroll 8
    for (int s = 1; s < NSP2; s++) {
        float v = g_bv2[s][t]; int c = g_bc2[s][t];
        if (v > bv) { bv = v; bc = c; }
    }
    g_idx[t] = bc;
}

__global__ void vq_reduce_k(const float* __restrict__ cb,
                            const float* __restrict__ Z,
                            float* __restrict__ out)
{
    __shared__ float ssum[256];
    __shared__ float sloss[256];
    const int b = blockIdx.x;
    const int tid = threadIdx.x;
    const int d = tid & 63;
    const int sg = tid >> 6;
    float sum = 0.f, loss = 0.f;
    for (int s = sg; s < SEQ; s += 4) {
        int c = g_idx[b * SEQ + s];
        float qv = cb[(long long)c * CBD + d];
        float zv = Z[((long long)b * SEQ + s) * CBD + d];
        sum += qv;
        float dd = qv - zv;
        loss += dd * dd;
    }
    ssum[tid] = sum; sloss[tid] = loss;
    __syncthreads();
    if (tid < 64)
        out[b * CBD + tid] = ssum[tid] + ssum[tid + 64] + ssum[tid + 128] + ssum[tid + 192];
    for (int st = 128; st > 0; st >>= 1) {
        if (tid < st) sloss[tid] += sloss[tid + st];
        __syncthreads();
    }
    if (tid == 0) g_part[b] = sloss[0];
}

__global__ void vq_finish_k(float* __restrict__ out, int out_size)
{
    if (threadIdx.x == 0 && out_size > NBAT * CBD) {
        float s = 0.f;
        for (int i = 0; i < NBAT; i++) s += g_part[i];
        out[NBAT * CBD] = s / (float)(TOK * CBD);
    }
}

// ---------------------------------------------------------------------------
// Launch
// ---------------------------------------------------------------------------
extern "C" void kernel_launch(void* const* d_in, const int* in_sizes, int n_in,
                              void* d_out, int out_size)
{
    (void)in_sizes; (void)n_in;
    const float* x    = (const float*)d_in[0];
    const float* w_in = (const float*)d_in[1];
    const float* b_in = (const float*)d_in[2];
    const float* pos  = (const float*)d_in[3];
    const float* ln1g = (const float*)d_in[4];
    const float* ln1b = (const float*)d_in[5];
    const float* wq   = (const float*)d_in[6];
    const float* wk   = (const float*)d_in[7];
    const float* wv   = (const float*)d_in[8];
    const float* wo   = (const float*)d_in[9];
    const float* ln2g = (const float*)d_in[10];
    const float* ln2b = (const float*)d_in[11];
    const float* fw1  = (const float*)d_in[12];
    const float* fb1  = (const float*)d_in[13];
    const float* fw2  = (const float*)d_in[14];
    const float* fb2  = (const float*)d_in[15];
    const float* lnfg = (const float*)d_in[16];
    const float* lnfb = (const float*)d_in[17];
    const float* wout = (const float*)d_in[18];
    const float* bout = (const float*)d_in[19];
    const float* cbk  = (const float*)d_in[20];
    float* out = (float*)d_out;

    float *h, *ln, *qb, *kb, *vb, *att, *ff, *z, *cbt;
    cudaGetSymbolAddress((void**)&h,   g_h);
    cudaGetSymbolAddress((void**)&ln,  g_lnb);
    cudaGetSymbolAddress((void**)&qb,  g_qb);
    cudaGetSymbolAddress((void**)&kb,  g_kb);
    cudaGetSymbolAddress((void**)&vb,  g_vb);
    cudaGetSymbolAddress((void**)&att, g_att);
    cudaGetSymbolAddress((void**)&ff,  g_ffb);
    cudaGetSymbolAddress((void**)&z,   g_z);
    cudaGetSymbolAddress((void**)&cbt, g_cbt);

    cudaFuncSetAttribute(tgemm_k, cudaFuncAttributeMaxDynamicSharedMemorySize, TG_SMEM);
    cudaFuncSetAttribute(vq_mma_k, cudaFuncAttributeMaxDynamicSharedMemorySize, TG_SMEM);
    cudaFuncSetAttribute(fattn_k, cudaFuncAttributeMaxDynamicSharedMemorySize, FA_SMEM);

    const dim3 g512(4, 64), g2048(16, 64), g64(1, 64);

    tgemm_k<<<g512, 256, TG_SMEM>>>(x, w_in, h, b_in, pos, DIMN, DIMN, EPI_BIAS_POS);

    for (int l = 0; l < 4; l++) {
        layernorm_k<<<TOK / 8, 256>>>(h, ln, ln1g + l * DIMN, ln1b + l * DIMN);
        tgemm_k<<<g512, 256, TG_SMEM>>>(ln, wq + (long long)l * DIMN * DIMN, qb, nullptr, nullptr, DIMN, DIMN, EPI_NONE);
        tgemm_k<<<g512, 256, TG_SMEM>>>(ln, wk + (long long)l * DIMN * DIMN, kb, nullptr, nullptr, DIMN, DIMN, EPI_NONE);
        tgemm_k<<<g512, 256, TG_SMEM>>>(ln, wv + (long long)l * DIMN * DIMN, vb, nullptr, nullptr, DIMN, DIMN, EPI_NONE);
        fattn_k<<<dim3(8, 128), 128, FA_SMEM>>>(qb, kb, vb, att);
        tgemm_k<<<g512, 256, TG_SMEM>>>(att, wo + (long long)l * DIMN * DIMN, h, nullptr, h, DIMN, DIMN, EPI_RES);
        layernorm_k<<<TOK / 8, 256>>>(h, ln, ln2g + l * DIMN, ln2b + l * DIMN);
        tgemm_k<<<g2048, 256, TG_SMEM>>>(ln, fw1 + (long long)l * DIMN * FFD, ff, fb1 + l * FFD, nullptr, FFD, DIMN, EPI_GELU_BIAS);
        tgemm_k<<<g512, 256, TG_SMEM>>>(ff, fw2 + (long long)l * FFD * DIMN, h, fb2 + l * DIMN, h, DIMN, FFD, EPI_RES_BIAS);
    }

    layernorm_k<<<TOK / 8, 256>>>(h, ln, lnfg, lnfb);
    tgemm_k<<<g64, 256, TG_SMEM>>>(ln, wout, z, bout, nullptr, CBD, DIMN, EPI_BIAS);

    cbt_k<<<dim3(CBSZ / 32, CBD / 32), dim3(32, 8)>>>(cbk);
    vq_mma_k<<<dim3(CBSZ / 128, TOK / 128), 256, TG_SMEM>>>(z, cbt, CBSZ, CBD);
    vq_combine_k<<<TOK / 256, 256>>>();
    vq_reduce_k<<<NBAT, 256>>>(cbk, z, out);
    vq_finish_k<<<1, 32>>>(out, out_size);
}